// round 16
// baseline (speedup 1.0000x reference)
#include <cuda_runtime.h>
#include <cuda_bf16.h>
#include <math.h>
#include <stdint.h>

#define Bq 2
#define NH 8
#define Gh 4
#define Tt 2048
#define Nn 2048
#define Dd 512
#define HALF (Nn/2)

#define SCALE 0.022097086912079612f   // 2048^-0.5

#define SZ_Q     ((long long)Bq * NH * Tt * Nn)
#define SZ_V     ((long long)Bq * 1  * Tt * Dd)
#define SZ_STATE ((long long)Bq * NH * Nn * Dd)
#define SZ_LAM   ((long long)Gh)

// ---------------- scratch (device globals, no allocation) ----------------
__device__ __align__(16) float g_cos[Tt * HALF];
__device__ __align__(16) float g_sin[Tt * HALF];
__device__ __align__(16) float g_QR[(size_t)Bq * NH * Tt * Nn];
__device__ __align__(16) float g_P [(size_t)Bq * NH * Tt * Nn];
__device__ __align__(16) float g_rows[(size_t)Bq * Gh * Tt];

// packed split: two floats -> bf16x2 hi + bf16x2 lo (per-lane RN)
__device__ __forceinline__ void split2(float x, float y, uint32_t& hi2, uint32_t& lo2) {
    __nv_bfloat162 h = __floats2bfloat162_rn(x, y);
    float2 hf = __bfloat1622float2(h);
    __nv_bfloat162 l = __floats2bfloat162_rn(x - hf.x, y - hf.y);
    hi2 = *(uint32_t*)&h;
    lo2 = *(uint32_t*)&l;
}

// ---------------- K1: rope tables (double precision) ----------------
__global__ void k_tables(const int* pos_offset_p) {
    int idx = blockIdx.x * blockDim.x + threadIdx.x;
    if (idx >= Tt * HALF) return;
    int t = idx / HALF;
    int c = idx % HALF;
    int off = pos_offset_p ? *pos_offset_p : 0;
    double freq = exp2(-(double)c / 64.0) / (2.0 * M_PI);
    double ang  = fmod((double)(off + t) * freq, 1.0) * (2.0 * M_PI);
    g_cos[idx] = (float)cos(ang);
    g_sin[idx] = (float)sin(ang);
}

// ---------------- K2: fused RoPE + exclusive prefix sum ----------------
__global__ void __launch_bounds__(256) k_ropeprefix(const float* __restrict__ Q) {
    int bh = blockIdx.y;
    int cp = blockIdx.x * 256 + threadIdx.x;        // 0..1023 pair index
    const float2* Qp = (const float2*)Q + ((size_t)bh * Tt * Nn >> 1) + cp;
    float2*      QRp = (float2*)g_QR   + ((size_t)bh * Tt * Nn >> 1) + cp;
    float2*      Pp  = (float2*)g_P    + ((size_t)bh * Tt * Nn >> 1) + cp;
    float2 acc = make_float2(0.f, 0.f);
    for (int t = 0; t < Tt; t++) {
        float cs = g_cos[t * HALF + cp];
        float sn = g_sin[t * HALF + cp];
        float2 q = Qp[(size_t)t * HALF];
        float2 o;
        o.x = q.x * cs - q.y * sn;
        o.y = q.x * sn + q.y * cs;
        QRp[(size_t)t * HALF] = o;
        Pp [(size_t)t * HALF] = acc;
        acc.x += o.x;
        acc.y += o.y;
    }
}

// ---------------- K4: rows[bg,t] = SCALE*(QR1[t].P1[t] - lam*QR2[t].P2[t]) ----------------
__global__ void __launch_bounds__(256) k_rowsum(const float* __restrict__ lambda_param) {
    int bg = blockIdx.y;
    int g  = bg % Gh;
    int w    = threadIdx.x >> 5;
    int lane = threadIdx.x & 31;
    int t = blockIdx.x * 8 + w;

    const float* q1 = g_QR + ((size_t)bg * 2) * Tt * Nn + (size_t)t * Nn;
    const float* q2 = q1 + (size_t)Tt * Nn;
    const float* p1 = g_P  + ((size_t)bg * 2) * Tt * Nn + (size_t)t * Nn;
    const float* p2 = p1 + (size_t)Tt * Nn;

    float r1 = 0.f, r2 = 0.f;
    for (int n = lane; n < Nn; n += 32) {
        r1 += q1[n] * p1[n];
        r2 += q2[n] * p2[n];
    }
#pragma unroll
    for (int o = 16; o; o >>= 1) {
        r1 += __shfl_xor_sync(0xffffffffu, r1, o);
        r2 += __shfl_xor_sync(0xffffffffu, r2, o);
    }
    if (lane == 0) {
        float lam = 1.f / (1.f + expf(-lambda_param[g]));
        g_rows[(size_t)bg * Tt + t] = SCALE * (r1 - lam * r2);
    }
}

// ---------------- tensor-core GEMM: direct LDG->split->STS, double-buffered planes ----------------
#define KPAD 40
#define PLANE_E (128 * KPAD)                 // 5120 bf16 per plane
#define PLANESET_B (4 * PLANE_E * 2)         // 40960 bytes (Ahi,Alo,Bhi,Blo)
#define SMEM_DYN (2 * PLANESET_B)            // 81920 bytes

#define MMA_BF16(C, A0, A1, A2, A3, B0, B1)                                   \
    asm volatile("mma.sync.aligned.m16n8k16.row.col.f32.bf16.bf16.f32 "       \
                 "{%0,%1,%2,%3}, {%4,%5,%6,%7}, {%8,%9}, {%0,%1,%2,%3};"      \
                 : "+f"((C)[0]), "+f"((C)[1]), "+f"((C)[2]), "+f"((C)[3])     \
                 : "r"(A0), "r"(A1), "r"(A2), "r"(A3), "r"(B0), "r"(B1))

extern __shared__ __align__(16) char dynsmem[];

__device__ __forceinline__ void compute_stage32(
        const __nv_bfloat16 (*sAhi)[KPAD], const __nv_bfloat16 (*sAlo)[KPAD],
        const __nv_bfloat16 (*sBhi)[KPAD], const __nv_bfloat16 (*sBlo)[KPAD],
        int wm, int wn, int lq, int lr, float c[2][8][4]) {
#pragma unroll
    for (int kk = 0; kk < 32; kk += 16) {
        uint32_t ah[2][4], al[2][4];
#pragma unroll
        for (int mt = 0; mt < 2; mt++) {
            int r = wm * 32 + mt * 16 + lq;
            int kc = kk + lr;
            ah[mt][0] = *(const uint32_t*)&sAhi[r][kc];
            ah[mt][1] = *(const uint32_t*)&sAhi[r + 8][kc];
            ah[mt][2] = *(const uint32_t*)&sAhi[r][kc + 8];
            ah[mt][3] = *(const uint32_t*)&sAhi[r + 8][kc + 8];
            al[mt][0] = *(const uint32_t*)&sAlo[r][kc];
            al[mt][1] = *(const uint32_t*)&sAlo[r + 8][kc];
            al[mt][2] = *(const uint32_t*)&sAlo[r][kc + 8];
            al[mt][3] = *(const uint32_t*)&sAlo[r + 8][kc + 8];
        }
#pragma unroll
        for (int nt = 0; nt < 8; nt++) {
            int n = wn * 64 + nt * 8 + lq;
            int kc = kk + lr;
            uint32_t b0h = *(const uint32_t*)&sBhi[n][kc];
            uint32_t b1h = *(const uint32_t*)&sBhi[n][kc + 8];
            uint32_t b0l = *(const uint32_t*)&sBlo[n][kc];
            uint32_t b1l = *(const uint32_t*)&sBlo[n][kc + 8];
#pragma unroll
            for (int mt = 0; mt < 2; mt++) {
                MMA_BF16(c[mt][nt], ah[mt][0], ah[mt][1], ah[mt][2], ah[mt][3], b0h, b1h);
                MMA_BF16(c[mt][nt], ah[mt][0], ah[mt][1], ah[mt][2], ah[mt][3], b0l, b1l);
                MMA_BF16(c[mt][nt], al[mt][0], al[mt][1], al[mt][2], al[mt][3], b0h, b1h);
            }
        }
    }
}

// ---------------- K5: out = QR @ state + rows[t]*V[t,d] ----------------
// A = QR[t][n] ([m][k] direct), B = state[n][d] ([k][d], transposed into planes)
__global__ void __launch_bounds__(256, 2) k_out_mma(const float* __restrict__ state,
                                                    const float* __restrict__ V,
                                                    float* __restrict__ out) {
    int bh = blockIdx.y;
    int b = bh >> 3, h = bh & 7;
    int row0 = (blockIdx.x >> 2) * 128;
    int col0 = (blockIdx.x & 3) * 128;

    const float* A = g_QR + (size_t)bh * Tt * Nn;   // [t][n]
    const float* B = state + (size_t)bh * Nn * Dd;  // [n][d]

    int tid = threadIdx.x, lane = tid & 31, w = tid >> 5;
    int wm = w >> 1, wn = w & 1;
    int lq = lane >> 2, lr = (lane & 3) * 2;

    float c[2][8][4];
#pragma unroll
    for (int mt = 0; mt < 2; mt++)
#pragma unroll
        for (int nt = 0; nt < 8; nt++)
#pragma unroll
            for (int q = 0; q < 4; q++) c[mt][nt][q] = 0.f;

    const int nK = Nn / 32;
    for (int it = 0; it < nK; it++) {
        int k0 = it * 32;
        char* pb = dynsmem + (it & 1) * PLANESET_B;
        __nv_bfloat16 (*sAhi)[KPAD] = (__nv_bfloat16 (*)[KPAD])(pb);
        __nv_bfloat16 (*sAlo)[KPAD] = (__nv_bfloat16 (*)[KPAD])(pb + PLANE_E * 2);
        __nv_bfloat16 (*sBhi)[KPAD] = (__nv_bfloat16 (*)[KPAD])(pb + 2 * PLANE_E * 2);
        __nv_bfloat16 (*sBlo)[KPAD] = (__nv_bfloat16 (*)[KPAD])(pb + 3 * PLANE_E * 2);

        // split A: direct [m][k] from GMEM (coalesced float2)
#pragma unroll
        for (int j = 0; j < 8; j++) {
            int idx = tid + j * 256;
            int m = idx >> 4, k = (idx & 15) * 2;
            float2 v = *(const float2*)&A[(size_t)(row0 + m) * Nn + k0 + k];
            uint32_t h2, l2;
            split2(v.x, v.y, h2, l2);
            *(uint32_t*)&sAhi[m][k] = h2;
            *(uint32_t*)&sAlo[m][k] = l2;
        }
        // split B: [k][d] from GMEM -> transposed planes [d][k] (coalesced along d)
#pragma unroll
        for (int j = 0; j < 8; j++) {
            int idx = tid + j * 256;
            int kp = idx >> 7, d = idx & 127;
            float x0 = B[(size_t)(k0 + 2 * kp) * Dd + col0 + d];
            float x1 = B[(size_t)(k0 + 2 * kp + 1) * Dd + col0 + d];
            uint32_t h2, l2;
            split2(x0, x1, h2, l2);
            *(uint32_t*)&sBhi[d][2 * kp] = h2;
            *(uint32_t*)&sBlo[d][2 * kp] = l2;
        }
        __syncthreads();
        compute_stage32(sAhi, sAlo, sBhi, sBlo, wm, wn, lq, lr, c);
        // no second sync: next split writes the other plane buffer; the write
        // to THIS buffer (it+2) is ordered after next stage's sync, and every
        // warp's compute(it) precedes its split(it+1) in program order.
    }

    const float* rows = g_rows + ((size_t)(b * Gh + (h >> 1))) * Tt;
    const float* Vb   = V + (size_t)b * Tt * Dd;
    float* o = out + (size_t)bh * Tt * Dd;
#pragma unroll
    for (int mt = 0; mt < 2; mt++) {
#pragma unroll
        for (int half = 0; half < 2; half++) {
            int r = row0 + wm * 32 + mt * 16 + lq + half * 8;
            float rowv = rows[r];
            const float2* vrow = (const float2*)&Vb[(size_t)r * Dd];
            float2* orow = (float2*)&o[(size_t)r * Dd];
#pragma unroll
            for (int nt = 0; nt < 8; nt++) {
                int cc = col0 + wn * 64 + nt * 8 + lr;
                float2 v = vrow[cc >> 1];
                float2 res;
                res.x = c[mt][nt][half * 2 + 0] + rowv * v.x;
                res.y = c[mt][nt][half * 2 + 1] + rowv * v.y;
                orow[cc >> 1] = res;
            }
        }
    }
}

// ---------------- K6: new_state = state + SCALE * QR^T @ V ----------------
// A = QR[t][n] -> planes [n][t]; B = V[t][d] -> planes [d][t]
__global__ void __launch_bounds__(256, 2) k_newstate_mma(const float* __restrict__ V,
                                                         const float* __restrict__ state,
                                                         float* __restrict__ ns_out) {
    int bh = blockIdx.y;
    int b = bh >> 3;
    int row0 = (blockIdx.x >> 2) * 128;   // n tile
    int col0 = (blockIdx.x & 3) * 128;    // d tile

    const float* A  = g_QR + (size_t)bh * Tt * Nn;  // [t][n]
    const float* Bv = V + (size_t)b * Tt * Dd;      // [t][d]

    int tid = threadIdx.x, lane = tid & 31, w = tid >> 5;
    int wm = w >> 1, wn = w & 1;
    int lq = lane >> 2, lr = (lane & 3) * 2;

    float c[2][8][4];
#pragma unroll
    for (int mt = 0; mt < 2; mt++)
#pragma unroll
        for (int nt = 0; nt < 8; nt++)
#pragma unroll
            for (int q = 0; q < 4; q++) c[mt][nt][q] = 0.f;

    const int nK = Tt / 32;
    for (int it = 0; it < nK; it++) {
        int k0 = it * 32;
        char* pb = dynsmem + (it & 1) * PLANESET_B;
        __nv_bfloat16 (*sAhi)[KPAD] = (__nv_bfloat16 (*)[KPAD])(pb);
        __nv_bfloat16 (*sAlo)[KPAD] = (__nv_bfloat16 (*)[KPAD])(pb + PLANE_E * 2);
        __nv_bfloat16 (*sBhi)[KPAD] = (__nv_bfloat16 (*)[KPAD])(pb + 2 * PLANE_E * 2);
        __nv_bfloat16 (*sBlo)[KPAD] = (__nv_bfloat16 (*)[KPAD])(pb + 3 * PLANE_E * 2);

        // split A: [k=t][n] from GMEM -> transposed planes [n][t] (coalesced along n)
#pragma unroll
        for (int j = 0; j < 8; j++) {
            int idx = tid + j * 256;
            int kp = idx >> 7, m = idx & 127;
            float x0 = A[(size_t)(k0 + 2 * kp) * Nn + row0 + m];
            float x1 = A[(size_t)(k0 + 2 * kp + 1) * Nn + row0 + m];
            uint32_t h2, l2;
            split2(x0, x1, h2, l2);
            *(uint32_t*)&sAhi[m][2 * kp] = h2;
            *(uint32_t*)&sAlo[m][2 * kp] = l2;
        }
        // split B: [k=t][d] from GMEM -> transposed planes [d][t]
#pragma unroll
        for (int j = 0; j < 8; j++) {
            int idx = tid + j * 256;
            int kp = idx >> 7, d = idx & 127;
            float x0 = Bv[(size_t)(k0 + 2 * kp) * Dd + col0 + d];
            float x1 = Bv[(size_t)(k0 + 2 * kp + 1) * Dd + col0 + d];
            uint32_t h2, l2;
            split2(x0, x1, h2, l2);
            *(uint32_t*)&sBhi[d][2 * kp] = h2;
            *(uint32_t*)&sBlo[d][2 * kp] = l2;
        }
        __syncthreads();
        compute_stage32(sAhi, sAlo, sBhi, sBlo, wm, wn, lq, lr, c);
    }

    const float* st = state + (size_t)bh * Nn * Dd;
    float* o = ns_out + (size_t)bh * Nn * Dd;
#pragma unroll
    for (int mt = 0; mt < 2; mt++) {
#pragma unroll
        for (int half = 0; half < 2; half++) {
            int r = row0 + wm * 32 + mt * 16 + lq + half * 8;
            const float2* srow = (const float2*)&st[(size_t)r * Dd];
            float2* orow = (float2*)&o[(size_t)r * Dd];
#pragma unroll
            for (int nt = 0; nt < 8; nt++) {
                int cc = col0 + wn * 64 + nt * 8 + lr;
                float2 s = srow[cc >> 1];
                float2 res;
                res.x = s.x + SCALE * c[mt][nt][half * 2 + 0];
                res.y = s.y + SCALE * c[mt][nt][half * 2 + 1];
                orow[cc >> 1] = res;
            }
        }
    }
}

// ---------------- launch ----------------
extern "C" void kernel_launch(void* const* d_in, const int* in_sizes, int n_in,
                              void* d_out, int out_size) {
    const float* Q     = nullptr;
    const float* V     = nullptr;
    const float* state = nullptr;
    const float* lam   = nullptr;
    const int*   pos   = nullptr;

    for (int i = 0; i < n_in; i++) {
        long long s = (long long)in_sizes[i];
        if      (s == SZ_Q)     Q     = (const float*)d_in[i];
        else if (s == SZ_V)     V     = (const float*)d_in[i];
        else if (s == SZ_STATE) state = (const float*)d_in[i];
        else if (s == SZ_LAM)   lam   = (const float*)d_in[i];
        else if (s == 1)        pos   = (const int*)d_in[i];
    }
    if (!Q     && n_in > 0) Q     = (const float*)d_in[0];
    if (!V     && n_in > 1) V     = (const float*)d_in[1];
    if (!state && n_in > 2) state = (const float*)d_in[2];
    if (!lam   && n_in > 3) lam   = (const float*)d_in[3];

    const size_t SEG = (size_t)16777216;
    float* out_t  = (float*)d_out;        // segment 0: output
    float* ns_out = (float*)d_out + SEG;  // segment 1: new_state

    cudaFuncSetAttribute(k_out_mma,      cudaFuncAttributeMaxDynamicSharedMemorySize, SMEM_DYN);
    cudaFuncSetAttribute(k_newstate_mma, cudaFuncAttributeMaxDynamicSharedMemorySize, SMEM_DYN);

    k_tables<<<(Tt * HALF + 255) / 256, 256>>>(pos);
    k_ropeprefix<<<dim3(4, Bq * NH), 256>>>(Q);
    k_rowsum<<<dim3(Tt / 8, Bq * Gh), 256>>>(lam);
    k_out_mma<<<dim3(64, Bq * NH), 256, SMEM_DYN>>>(state, V, out_t);
    k_newstate_mma<<<dim3(64, Bq * NH), 256, SMEM_DYN>>>(V, state, ns_out);
}

// round 17
// speedup vs baseline: 1.4120x; 1.4120x over previous
#include <cuda_runtime.h>
#include <cuda_bf16.h>
#include <math.h>
#include <stdint.h>

#define Bq 2
#define NH 8
#define Gh 4
#define Tt 2048
#define Nn 2048
#define Dd 512
#define HALF (Nn/2)
#define NCHUNK 16
#define CLEN (Tt / NCHUNK)   // 128

#define SCALE 0.022097086912079612f   // 2048^-0.5

#define SZ_Q     ((long long)Bq * NH * Tt * Nn)
#define SZ_V     ((long long)Bq * 1  * Tt * Dd)
#define SZ_STATE ((long long)Bq * NH * Nn * Dd)
#define SZ_LAM   ((long long)Gh)

// ---------------- scratch (device globals, no allocation) ----------------
__device__ __align__(16) float g_cos[Tt * HALF];
__device__ __align__(16) float g_sin[Tt * HALF];
__device__ __align__(16) float g_QR[(size_t)Bq * NH * Tt * Nn];
__device__ __align__(16) float g_P [(size_t)Bq * NH * Tt * Nn];
__device__ __align__(16) float g_rows[(size_t)Bq * Gh * Tt];
__device__ __align__(16) float2 g_csum[(size_t)Bq * NH * NCHUNK * HALF];  // per-chunk sums (pairs)

// packed split: two floats -> bf16x2 hi + bf16x2 lo (per-lane RN)
__device__ __forceinline__ void split2(float x, float y, uint32_t& hi2, uint32_t& lo2) {
    __nv_bfloat162 h = __floats2bfloat162_rn(x, y);
    float2 hf = __bfloat1622float2(h);
    __nv_bfloat162 l = __floats2bfloat162_rn(x - hf.x, y - hf.y);
    hi2 = *(uint32_t*)&h;
    lo2 = *(uint32_t*)&l;
}

// ---------------- K1: rope tables (double precision) ----------------
__global__ void k_tables(const int* pos_offset_p) {
    int idx = blockIdx.x * blockDim.x + threadIdx.x;
    if (idx >= Tt * HALF) return;
    int t = idx / HALF;
    int c = idx % HALF;
    int off = pos_offset_p ? *pos_offset_p : 0;
    double freq = exp2(-(double)c / 64.0) / (2.0 * M_PI);
    double ang  = fmod((double)(off + t) * freq, 1.0) * (2.0 * M_PI);
    g_cos[idx] = (float)cos(ang);
    g_sin[idx] = (float)sin(ang);
}

// ---------------- K2a: rope + per-chunk partial sums ----------------
// thread = (bh, chunk, cp). loop 128 t's: rope, write QR, accumulate chunk sum.
__global__ void __launch_bounds__(256) k_rope_csum(const float* __restrict__ Q) {
    int bh  = blockIdx.y;
    int idx = blockIdx.x * 256 + threadIdx.x;       // 0..16383
    int chunk = idx >> 10;                           // 0..15
    int cp    = idx & 1023;                          // pair index
    int t0 = chunk * CLEN;
    const float2* Qp = (const float2*)Q + ((size_t)bh * Tt * Nn >> 1) + (size_t)t0 * HALF + cp;
    float2*      QRp = (float2*)g_QR   + ((size_t)bh * Tt * Nn >> 1) + (size_t)t0 * HALF + cp;
    float2 acc = make_float2(0.f, 0.f);
#pragma unroll 4
    for (int i = 0; i < CLEN; i++) {
        int t = t0 + i;
        float cs = g_cos[t * HALF + cp];
        float sn = g_sin[t * HALF + cp];
        float2 q = Qp[(size_t)i * HALF];
        float2 o;
        o.x = q.x * cs - q.y * sn;
        o.y = q.x * sn + q.y * cs;
        QRp[(size_t)i * HALF] = o;
        acc.x += o.x;
        acc.y += o.y;
    }
    g_csum[((size_t)bh * NCHUNK + chunk) * HALF + cp] = acc;
}

// ---------------- K2b: local exclusive prefix with chunk offsets -> g_P ----------------
__global__ void __launch_bounds__(256) k_prefix2(int dummy) {
    int bh  = blockIdx.y;
    int idx = blockIdx.x * 256 + threadIdx.x;
    int chunk = idx >> 10;
    int cp    = idx & 1023;
    int t0 = chunk * CLEN;

    // offset = sum of earlier chunks' sums (in chunk order = serial-consistent)
    float2 acc = make_float2(0.f, 0.f);
    const float2* cs = g_csum + (size_t)bh * NCHUNK * HALF + cp;
    for (int c = 0; c < NCHUNK; c++) {
        if (c < chunk) {
            float2 v = cs[(size_t)c * HALF];
            acc.x += v.x;
            acc.y += v.y;
        }
    }

    const float2* QRp = (const float2*)g_QR + ((size_t)bh * Tt * Nn >> 1) + (size_t)t0 * HALF + cp;
    float2*       Pp  = (float2*)g_P        + ((size_t)bh * Tt * Nn >> 1) + (size_t)t0 * HALF + cp;
#pragma unroll 4
    for (int i = 0; i < CLEN; i++) {
        Pp[(size_t)i * HALF] = acc;
        float2 o = QRp[(size_t)i * HALF];
        acc.x += o.x;
        acc.y += o.y;
    }
    (void)dummy;
}

// ---------------- K4: rows[bg,t] = SCALE*(QR1[t].P1[t] - lam*QR2[t].P2[t]) ----------------
__global__ void __launch_bounds__(256) k_rowsum(const float* __restrict__ lambda_param) {
    int bg = blockIdx.y;
    int g  = bg % Gh;
    int w    = threadIdx.x >> 5;
    int lane = threadIdx.x & 31;
    int t = blockIdx.x * 8 + w;

    const float* q1 = g_QR + ((size_t)bg * 2) * Tt * Nn + (size_t)t * Nn;
    const float* q2 = q1 + (size_t)Tt * Nn;
    const float* p1 = g_P  + ((size_t)bg * 2) * Tt * Nn + (size_t)t * Nn;
    const float* p2 = p1 + (size_t)Tt * Nn;

    float r1 = 0.f, r2 = 0.f;
    for (int n = lane; n < Nn; n += 32) {
        r1 += q1[n] * p1[n];
        r2 += q2[n] * p2[n];
    }
#pragma unroll
    for (int o = 16; o; o >>= 1) {
        r1 += __shfl_xor_sync(0xffffffffu, r1, o);
        r2 += __shfl_xor_sync(0xffffffffu, r2, o);
    }
    if (lane == 0) {
        float lam = 1.f / (1.f + expf(-lambda_param[g]));
        g_rows[(size_t)bg * Tt + t] = SCALE * (r1 - lam * r2);
    }
}

// ---------------- tensor-core GEMM (R15 config: cp.async staging, packed split) ----------------
#define KPAD 40
#define PLANE_E (128 * KPAD)
#define F32_STAGE 8192
#define PLANES_OFF (2 * F32_STAGE * 4)      // 65536 bytes
#define SMEM_DYN (PLANES_OFF + 4 * PLANE_E * 2)   // 106496 bytes

#define MMA_BF16(C, A0, A1, A2, A3, B0, B1)                                   \
    asm volatile("mma.sync.aligned.m16n8k16.row.col.f32.bf16.bf16.f32 "       \
                 "{%0,%1,%2,%3}, {%4,%5,%6,%7}, {%8,%9}, {%0,%1,%2,%3};"      \
                 : "+f"((C)[0]), "+f"((C)[1]), "+f"((C)[2]), "+f"((C)[3])     \
                 : "r"(A0), "r"(A1), "r"(A2), "r"(A3), "r"(B0), "r"(B1))

#define CP16(smem_u32, gptr) \
    asm volatile("cp.async.cg.shared.global [%0], [%1], 16;" :: "r"(smem_u32), "l"(gptr))

extern __shared__ __align__(16) char dynsmem[];

__device__ __forceinline__ void cpA128x32(float* dst, const float* src, int ld,
                                          int row0, int k0, int tid) {
#pragma unroll
    for (int i = 0; i < 4; i++) {
        int chunk = tid + i * 256;
        int r = chunk >> 3, ch = chunk & 7;
        CP16((uint32_t)__cvta_generic_to_shared(dst + r * 32 + ch * 4),
             src + (size_t)(row0 + r) * ld + k0 + ch * 4);
    }
}

__device__ __forceinline__ void cpB32x128(float* dst, const float* src, int ld,
                                          int k0, int col0, int tid) {
#pragma unroll
    for (int i = 0; i < 4; i++) {
        int chunk = tid + i * 256;
        int kr = chunk >> 5, ch = chunk & 31;
        CP16((uint32_t)__cvta_generic_to_shared(dst + kr * 128 + ch * 4),
             src + (size_t)(k0 + kr) * ld + col0 + ch * 4);
    }
}

__device__ __forceinline__ void splitA_direct(const float* s32,
                                              __nv_bfloat16 (*hi)[KPAD],
                                              __nv_bfloat16 (*lo)[KPAD], int tid) {
#pragma unroll
    for (int j = 0; j < 8; j++) {
        int idx = tid + j * 256;
        int m = idx >> 4, k = (idx & 15) * 2;
        float2 v = *(const float2*)&s32[m * 32 + k];
        uint32_t h2, l2;
        split2(v.x, v.y, h2, l2);
        *(uint32_t*)&hi[m][k] = h2;
        *(uint32_t*)&lo[m][k] = l2;
    }
}

__device__ __forceinline__ void splitB_trans(const float* s32,
                                             __nv_bfloat16 (*hi)[KPAD],
                                             __nv_bfloat16 (*lo)[KPAD], int tid) {
#pragma unroll
    for (int j = 0; j < 8; j++) {
        int idx = tid + j * 256;
        int kp = idx >> 7, d = idx & 127;
        float x0 = s32[(2 * kp) * 128 + d];
        float x1 = s32[(2 * kp + 1) * 128 + d];
        uint32_t h2, l2;
        split2(x0, x1, h2, l2);
        *(uint32_t*)&hi[d][2 * kp] = h2;
        *(uint32_t*)&lo[d][2 * kp] = l2;
    }
}

__device__ __forceinline__ void compute_stage32(
        const __nv_bfloat16 (*sAhi)[KPAD], const __nv_bfloat16 (*sAlo)[KPAD],
        const __nv_bfloat16 (*sBhi)[KPAD], const __nv_bfloat16 (*sBlo)[KPAD],
        int wm, int wn, int lq, int lr, float c[2][8][4]) {
#pragma unroll
    for (int kk = 0; kk < 32; kk += 16) {
        uint32_t ah[2][4], al[2][4];
#pragma unroll
        for (int mt = 0; mt < 2; mt++) {
            int r = wm * 32 + mt * 16 + lq;
            int kc = kk + lr;
            ah[mt][0] = *(const uint32_t*)&sAhi[r][kc];
            ah[mt][1] = *(const uint32_t*)&sAhi[r + 8][kc];
            ah[mt][2] = *(const uint32_t*)&sAhi[r][kc + 8];
            ah[mt][3] = *(const uint32_t*)&sAhi[r + 8][kc + 8];
            al[mt][0] = *(const uint32_t*)&sAlo[r][kc];
            al[mt][1] = *(const uint32_t*)&sAlo[r + 8][kc];
            al[mt][2] = *(const uint32_t*)&sAlo[r][kc + 8];
            al[mt][3] = *(const uint32_t*)&sAlo[r + 8][kc + 8];
        }
#pragma unroll
        for (int nt = 0; nt < 8; nt++) {
            int n = wn * 64 + nt * 8 + lq;
            int kc = kk + lr;
            uint32_t b0h = *(const uint32_t*)&sBhi[n][kc];
            uint32_t b1h = *(const uint32_t*)&sBhi[n][kc + 8];
            uint32_t b0l = *(const uint32_t*)&sBlo[n][kc];
            uint32_t b1l = *(const uint32_t*)&sBlo[n][kc + 8];
#pragma unroll
            for (int mt = 0; mt < 2; mt++) {
                MMA_BF16(c[mt][nt], ah[mt][0], ah[mt][1], ah[mt][2], ah[mt][3], b0h, b1h);
                MMA_BF16(c[mt][nt], ah[mt][0], ah[mt][1], ah[mt][2], ah[mt][3], b0l, b1l);
                MMA_BF16(c[mt][nt], al[mt][0], al[mt][1], al[mt][2], al[mt][3], b0h, b1h);
            }
        }
    }
}

// ---------------- K5: out = QR @ state + rows[t]*V[t,d] ----------------
__global__ void __launch_bounds__(256, 2) k_out_mma(const float* __restrict__ state,
                                                    const float* __restrict__ V,
                                                    float* __restrict__ out) {
    int bh = blockIdx.y;
    int b = bh >> 3, h = bh & 7;
    int row0 = (blockIdx.x >> 2) * 128;
    int col0 = (blockIdx.x & 3) * 128;

    const float* A = g_QR + (size_t)bh * Tt * Nn;   // [t][n]
    const float* B = state + (size_t)bh * Nn * Dd;  // [n][d]

    float* f32 = (float*)dynsmem;
    __nv_bfloat16 (*sAhi)[KPAD] = (__nv_bfloat16 (*)[KPAD])(dynsmem + PLANES_OFF);
    __nv_bfloat16 (*sAlo)[KPAD] = (__nv_bfloat16 (*)[KPAD])(dynsmem + PLANES_OFF + PLANE_E * 2);
    __nv_bfloat16 (*sBhi)[KPAD] = (__nv_bfloat16 (*)[KPAD])(dynsmem + PLANES_OFF + 2 * PLANE_E * 2);
    __nv_bfloat16 (*sBlo)[KPAD] = (__nv_bfloat16 (*)[KPAD])(dynsmem + PLANES_OFF + 3 * PLANE_E * 2);

    int tid = threadIdx.x, lane = tid & 31, w = tid >> 5;
    int wm = w >> 1, wn = w & 1;
    int lq = lane >> 2, lr = (lane & 3) * 2;

    float c[2][8][4];
#pragma unroll
    for (int mt = 0; mt < 2; mt++)
#pragma unroll
        for (int nt = 0; nt < 8; nt++)
#pragma unroll
            for (int q = 0; q < 4; q++) c[mt][nt][q] = 0.f;

    const int nK = Nn / 32;
    cpA128x32(f32, A, Nn, row0, 0, tid);
    cpB32x128(f32 + 4096, B, Dd, 0, col0, tid);
    asm volatile("cp.async.commit_group;");

    for (int it = 0; it < nK; it++) {
        if (it + 1 < nK) {
            float* nf = f32 + ((it + 1) & 1) * F32_STAGE;
            cpA128x32(nf, A, Nn, row0, (it + 1) * 32, tid);
            cpB32x128(nf + 4096, B, Dd, (it + 1) * 32, col0, tid);
            asm volatile("cp.async.commit_group;");
            asm volatile("cp.async.wait_group 1;");
        } else {
            asm volatile("cp.async.wait_group 0;");
        }
        __syncthreads();
        const float* cf = f32 + (it & 1) * F32_STAGE;
        splitA_direct(cf, sAhi, sAlo, tid);
        splitB_trans(cf + 4096, sBhi, sBlo, tid);
        __syncthreads();
        compute_stage32(sAhi, sAlo, sBhi, sBlo, wm, wn, lq, lr, c);
        __syncthreads();
    }

    const float* rows = g_rows + ((size_t)(b * Gh + (h >> 1))) * Tt;
    const float* Vb   = V + (size_t)b * Tt * Dd;
    float* o = out + (size_t)bh * Tt * Dd;
#pragma unroll
    for (int mt = 0; mt < 2; mt++) {
#pragma unroll
        for (int half = 0; half < 2; half++) {
            int r = row0 + wm * 32 + mt * 16 + lq + half * 8;
            float rowv = rows[r];
            const float2* vrow = (const float2*)&Vb[(size_t)r * Dd];
            float2* orow = (float2*)&o[(size_t)r * Dd];
#pragma unroll
            for (int nt = 0; nt < 8; nt++) {
                int cc = col0 + wn * 64 + nt * 8 + lr;
                float2 v = vrow[cc >> 1];
                float2 res;
                res.x = c[mt][nt][half * 2 + 0] + rowv * v.x;
                res.y = c[mt][nt][half * 2 + 1] + rowv * v.y;
                orow[cc >> 1] = res;
            }
        }
    }
}

// ---------------- K6: new_state = state + SCALE * QR^T @ V ----------------
__global__ void __launch_bounds__(256, 2) k_newstate_mma(const float* __restrict__ V,
                                                         const float* __restrict__ state,
                                                         float* __restrict__ ns_out) {
    int bh = blockIdx.y;
    int b = bh >> 3;
    int row0 = (blockIdx.x >> 2) * 128;   // n tile
    int col0 = (blockIdx.x & 3) * 128;    // d tile

    const float* A  = g_QR + (size_t)bh * Tt * Nn;  // [t][n]
    const float* Bv = V + (size_t)b * Tt * Dd;      // [t][d]

    float* f32 = (float*)dynsmem;
    __nv_bfloat16 (*sAhi)[KPAD] = (__nv_bfloat16 (*)[KPAD])(dynsmem + PLANES_OFF);
    __nv_bfloat16 (*sAlo)[KPAD] = (__nv_bfloat16 (*)[KPAD])(dynsmem + PLANES_OFF + PLANE_E * 2);
    __nv_bfloat16 (*sBhi)[KPAD] = (__nv_bfloat16 (*)[KPAD])(dynsmem + PLANES_OFF + 2 * PLANE_E * 2);
    __nv_bfloat16 (*sBlo)[KPAD] = (__nv_bfloat16 (*)[KPAD])(dynsmem + PLANES_OFF + 3 * PLANE_E * 2);

    int tid = threadIdx.x, lane = tid & 31, w = tid >> 5;
    int wm = w >> 1, wn = w & 1;
    int lq = lane >> 2, lr = (lane & 3) * 2;

    float c[2][8][4];
#pragma unroll
    for (int mt = 0; mt < 2; mt++)
#pragma unroll
        for (int nt = 0; nt < 8; nt++)
#pragma unroll
            for (int q = 0; q < 4; q++) c[mt][nt][q] = 0.f;

    const int nK = Tt / 32;
    cpB32x128(f32, A, Nn, 0, row0, tid);
    cpB32x128(f32 + 4096, Bv, Dd, 0, col0, tid);
    asm volatile("cp.async.commit_group;");

    for (int it = 0; it < nK; it++) {
        if (it + 1 < nK) {
            float* nf = f32 + ((it + 1) & 1) * F32_STAGE;
            cpB32x128(nf, A, Nn, (it + 1) * 32, row0, tid);
            cpB32x128(nf + 4096, Bv, Dd, (it + 1) * 32, col0, tid);
            asm volatile("cp.async.commit_group;");
            asm volatile("cp.async.wait_group 1;");
        } else {
            asm volatile("cp.async.wait_group 0;");
        }
        __syncthreads();
        const float* cf = f32 + (it & 1) * F32_STAGE;
        splitB_trans(cf, sAhi, sAlo, tid);          // QR^T: [n][t]
        splitB_trans(cf + 4096, sBhi, sBlo, tid);   // V^T:  [d][t]
        __syncthreads();
        compute_stage32(sAhi, sAlo, sBhi, sBlo, wm, wn, lq, lr, c);
        __syncthreads();
    }

    const float* st = state + (size_t)bh * Nn * Dd;
    float* o = ns_out + (size_t)bh * Nn * Dd;
#pragma unroll
    for (int mt = 0; mt < 2; mt++) {
#pragma unroll
        for (int half = 0; half < 2; half++) {
            int r = row0 + wm * 32 + mt * 16 + lq + half * 8;
            const float2* srow = (const float2*)&st[(size_t)r * Dd];
            float2* orow = (float2*)&o[(size_t)r * Dd];
#pragma unroll
            for (int nt = 0; nt < 8; nt++) {
                int cc = col0 + wn * 64 + nt * 8 + lr;
                float2 s = srow[cc >> 1];
                float2 res;
                res.x = s.x + SCALE * c[mt][nt][half * 2 + 0];
                res.y = s.y + SCALE * c[mt][nt][half * 2 + 1];
                orow[cc >> 1] = res;
            }
        }
    }
}

// ---------------- launch ----------------
extern "C" void kernel_launch(void* const* d_in, const int* in_sizes, int n_in,
                              void* d_out, int out_size) {
    const float* Q     = nullptr;
    const float* V     = nullptr;
    const float* state = nullptr;
    const float* lam   = nullptr;
    const int*   pos   = nullptr;

    for (int i = 0; i < n_in; i++) {
        long long s = (long long)in_sizes[i];
        if      (s == SZ_Q)     Q     = (const float*)d_in[i];
        else if (s == SZ_V)     V     = (const float*)d_in[i];
        else if (s == SZ_STATE) state = (const float*)d_in[i];
        else if (s == SZ_LAM)   lam   = (const float*)d_in[i];
        else if (s == 1)        pos   = (const int*)d_in[i];
    }
    if (!Q     && n_in > 0) Q     = (const float*)d_in[0];
    if (!V     && n_in > 1) V     = (const float*)d_in[1];
    if (!state && n_in > 2) state = (const float*)d_in[2];
    if (!lam   && n_in > 3) lam   = (const float*)d_in[3];

    const size_t SEG = (size_t)16777216;
    float* out_t  = (float*)d_out;        // segment 0: output
    float* ns_out = (float*)d_out + SEG;  // segment 1: new_state

    cudaFuncSetAttribute(k_out_mma,      cudaFuncAttributeMaxDynamicSharedMemorySize, SMEM_DYN);
    cudaFuncSetAttribute(k_newstate_mma, cudaFuncAttributeMaxDynamicSharedMemorySize, SMEM_DYN);

    k_tables<<<(Tt * HALF + 255) / 256, 256>>>(pos);
    // parallel two-pass scan: (NCHUNK*HALF)/256 = 64 blocks per bh
    k_rope_csum<<<dim3(64, Bq * NH), 256>>>(Q);
    k_prefix2<<<dim3(64, Bq * NH), 256>>>(0);
    k_rowsum<<<dim3(Tt / 8, Bq * Gh), 256>>>(lam);
    k_out_mma<<<dim3(64, Bq * NH), 256, SMEM_DYN>>>(state, V, out_t);
    k_newstate_mma<<<dim3(64, Bq * NH), 256, SMEM_DYN>>>(V, state, ns_out);
}